// round 8
// baseline (speedup 1.0000x reference)
#include <cuda_runtime.h>
#include <cstdint>

// ---------------------------------------------------------------------------
// out[8192,1000] = sign(X[8192,12288]) @ sign(W[1000,12288])^T
// Path: fp32 -> s8 (+1/-1), legacy IMMA mma.sync m16n8k32 s8.s8.s32 (exact),
// cp.async 3-stage pipeline, ldmatrix operand fetch. No sm_103a-only PTX.
// ---------------------------------------------------------------------------
#define M_DIM   8192
#define N_DIM   1000
#define NP      1024
#define D_DIM   12288
#define KCHUNK  128
#define NCHUNKS 96          // 12288 / 128
#define TM      256
#define TN      128
#define STAGES  3
#define A_STAGE_BYTES (TM * KCHUNK)              // 32768
#define B_STAGE_BYTES (TN * KCHUNK)              // 16384
#define STAGE_BYTES   (A_STAGE_BYTES + B_STAGE_BYTES)  // 49152
#define SMEM_REQ      (STAGES * STAGE_BYTES)     // 147456 (144 KB)

// s8 sign buffers (device globals: allocation-free, graph-safe)
__device__ uint8_t g_a8[(size_t)M_DIM * D_DIM];   // ~100.7 MB
__device__ uint8_t g_w8[(size_t)NP * D_DIM];      // ~12.6 MB

// ============================ PTX helpers ==================================
__device__ __forceinline__ uint32_t smem_to_u32(const void* p) {
    uint32_t a;
    asm("{ .reg .u64 t; cvta.to.shared.u64 t, %1; cvt.u32.u64 %0, t; }"
        : "=r"(a) : "l"(p));
    return a;
}

__device__ __forceinline__ void cp_async16(uint32_t saddr, const void* gptr) {
    asm volatile("cp.async.cg.shared.global [%0], [%1], 16;"
                 :: "r"(saddr), "l"(gptr));
}
#define CP_COMMIT() asm volatile("cp.async.commit_group;" ::: "memory")
#define CP_WAIT(n)  asm volatile("cp.async.wait_group %0;" :: "n"(n) : "memory")

__device__ __forceinline__ void ldsm_x4(uint32_t* r, uint32_t addr) {
    asm volatile("ldmatrix.sync.aligned.m8n8.x4.shared.b16 {%0,%1,%2,%3}, [%4];"
                 : "=r"(r[0]), "=r"(r[1]), "=r"(r[2]), "=r"(r[3])
                 : "r"(addr));
}

__device__ __forceinline__ void mma_s8(int* c, const uint32_t* a, const uint32_t* b) {
    asm volatile(
        "mma.sync.aligned.m16n8k32.row.col.s32.s8.s8.s32 "
        "{%0,%1,%2,%3}, {%4,%5,%6,%7}, {%8,%9}, {%0,%1,%2,%3};"
        : "+r"(c[0]), "+r"(c[1]), "+r"(c[2]), "+r"(c[3])
        : "r"(a[0]), "r"(a[1]), "r"(a[2]), "r"(a[3]),
          "r"(b[0]), "r"(b[1]));
}

// SW128 swizzle on byte offsets within a [rows x 128B] tile
#define SWZ(off) ((off) ^ (((off) >> 3) & 0x70))

// =========================== conversion kernels ============================
// fp32 -> s8 sign: x > 0 -> +1 (0x01), else -1 (0xFF). Exact.
__device__ __forceinline__ uint32_t sign4s8(float4 v) {
    uint32_t b0 = (v.x > 0.0f) ? 0x01u : 0xFFu;
    uint32_t b1 = (v.y > 0.0f) ? 0x01u : 0xFFu;
    uint32_t b2 = (v.z > 0.0f) ? 0x01u : 0xFFu;
    uint32_t b3 = (v.w > 0.0f) ? 0x01u : 0xFFu;
    return b0 | (b1 << 8) | (b2 << 16) | (b3 << 24);
}

__global__ __launch_bounds__(256)
void conv_sign_A(const float* __restrict__ in, uint8_t* __restrict__ out, int n16) {
    int u = blockIdx.x * blockDim.x + threadIdx.x;
    if (u >= n16) return;
    const float4* p = reinterpret_cast<const float4*>(in) + (size_t)u * 4;
    *reinterpret_cast<uint4*>(out + (size_t)u * 16) =
        make_uint4(sign4s8(p[0]), sign4s8(p[1]), sign4s8(p[2]), sign4s8(p[3]));
}

// W: [1000,12288] -> padded [1024,12288]; rows >= 1000 zeroed (products = 0).
__global__ __launch_bounds__(256)
void conv_sign_W(const float* __restrict__ in, uint8_t* __restrict__ out) {
    int u = blockIdx.x * blockDim.x + threadIdx.x;  // 16B unit index
    const int UPR = D_DIM / 16;                      // 768 per row
    if (u >= NP * UPR) return;
    int row = u / UPR;
    int cu  = u - row * UPR;
    uint4 v = make_uint4(0u, 0u, 0u, 0u);
    if (row < N_DIM) {
        const float4* p = reinterpret_cast<const float4*>(
            in + (size_t)row * D_DIM + cu * 16);
        v = make_uint4(sign4s8(p[0]), sign4s8(p[1]), sign4s8(p[2]), sign4s8(p[3]));
    }
    *reinterpret_cast<uint4*>(out + (size_t)u * 16) = v;
}

// ============================== GEMM kernel ================================
// 512 threads = 16 warps, warp grid 4(M) x 4(N): warp tile 64 x 32.
// Per warp per k32 step: 4 m16 tiles x 4 n8 tiles = 16 IMMA.
__global__ __launch_bounds__(512, 1)
void bgemm_imma_kernel(const uint8_t* __restrict__ A8,
                       const uint8_t* __restrict__ W8,
                       float* __restrict__ out)
{
    extern __shared__ char smem[];
    const uint32_t sbase = smem_to_u32(smem);
    const int tid  = threadIdx.x;
    const int warp = tid >> 5;
    const int lane = tid & 31;
    const int wm   = warp & 3;       // M group (64 rows)
    const int wn   = warp >> 2;      // N group (32 cols)
    const int mBase = blockIdx.y * TM;
    const int nBase = blockIdx.x * TN;

    // ldmatrix lane base offsets (unswizzled); XOR mask constant per lane.
    const uint32_t xm = (uint32_t)(lane & 7) << 4;
    // A: row = wm*64 + mt*16 + ((lane>>3)&1)*8 + (lane&7); col = ks*32 + (lane>>4)*16
    const uint32_t a_base =
        (uint32_t)((wm * 64 + ((lane >> 3) & 1) * 8 + (lane & 7)) * KCHUNK
                   + (lane >> 4) * 16);
    // B: row = wn*32 + np*16 + (lane>>4)*8 + (lane&7); col = ks*32 + ((lane>>3)&1)*16
    const uint32_t b_base =
        (uint32_t)((wn * 32 + (lane >> 4) * 8 + (lane & 7)) * KCHUNK
                   + ((lane >> 3) & 1) * 16);

    int acc[16][4];
#pragma unroll
    for (int t = 0; t < 16; t++)
#pragma unroll
        for (int r = 0; r < 4; r++) acc[t][r] = 0;

    // --- stage loader: 16B cp.async per unit; A 2048 units, B 1024 units ---
    auto load_stage = [&](int stage, int chunk) {
        const int kByte = chunk * KCHUNK;
        const uint32_t sA = sbase + stage * STAGE_BYTES;
        const uint32_t sB = sA + A_STAGE_BYTES;
#pragma unroll
        for (int l = 0; l < 4; l++) {          // A: 4 units per thread
            int u = tid + l * 512;
            int row = u >> 3, c = u & 7;
            uint32_t d = (uint32_t)(row * KCHUNK + c * 16);
            cp_async16(sA + SWZ(d),
                       A8 + (size_t)(mBase + row) * D_DIM + kByte + c * 16);
        }
#pragma unroll
        for (int l = 0; l < 2; l++) {          // B: 2 units per thread
            int u = tid + l * 512;
            int row = u >> 3, c = u & 7;
            uint32_t d = (uint32_t)(row * KCHUNK + c * 16);
            cp_async16(sB + SWZ(d),
                       W8 + (size_t)(nBase + row) * D_DIM + kByte + c * 16);
        }
    };

    // --- compute one 128B K-chunk from a stage ---
    auto compute_stage = [&](int stage) {
        const uint32_t sA = sbase + stage * STAGE_BYTES;
        const uint32_t sB = sA + A_STAGE_BYTES;
#pragma unroll
        for (int ks = 0; ks < 4; ks++) {
            uint32_t a[4][4];
#pragma unroll
            for (int mt = 0; mt < 4; mt++)
                ldsm_x4(a[mt], sA + ((a_base + mt * 16 * KCHUNK + ks * 32) ^ xm));
            uint32_t b[2][4];
#pragma unroll
            for (int np = 0; np < 2; np++)
                ldsm_x4(b[np], sB + ((b_base + np * 16 * KCHUNK + ks * 32) ^ xm));
#pragma unroll
            for (int mt = 0; mt < 4; mt++)
#pragma unroll
                for (int nt = 0; nt < 4; nt++)
                    mma_s8(acc[mt * 4 + nt], a[mt], &b[nt >> 1][(nt & 1) * 2]);
        }
    };

    // --- 3-stage pipeline ---
    load_stage(0, 0); CP_COMMIT();
    load_stage(1, 1); CP_COMMIT();
    for (int i = 0; i < NCHUNKS; i++) {
        if (i + 2 < NCHUNKS) load_stage((i + 2) % STAGES, i + 2);
        CP_COMMIT();
        CP_WAIT(2);
        __syncthreads();
        compute_stage(i % STAGES);
        __syncthreads();
    }

    // --- epilogue: s32 -> f32 (exact), guarded stores ---
#pragma unroll
    for (int mt = 0; mt < 4; mt++) {
        int m0 = mBase + wm * 64 + mt * 16 + (lane >> 2);
#pragma unroll
        for (int nt = 0; nt < 4; nt++) {
            int n = nBase + wn * 32 + nt * 8 + (lane & 3) * 2;
            if (n < N_DIM) {
                const int* c = acc[mt * 4 + nt];
                float2 v0 = make_float2((float)c[0], (float)c[1]);
                float2 v1 = make_float2((float)c[2], (float)c[3]);
                *reinterpret_cast<float2*>(out + (size_t)m0 * N_DIM + n) = v0;
                *reinterpret_cast<float2*>(out + (size_t)(m0 + 8) * N_DIM + n) = v1;
            }
        }
    }
}

// =============================== launcher ==================================
extern "C" void kernel_launch(void* const* d_in, const int* in_sizes, int n_in,
                              void* d_out, int out_size) {
    const float* inp = (const float*)d_in[0];   // [8192, 12288]
    const float* wt  = (const float*)d_in[1];   // [1000, 12288]
    float* out = (float*)d_out;                 // [8192, 1000]

    uint8_t* a8 = nullptr;
    uint8_t* w8 = nullptr;
    cudaGetSymbolAddress((void**)&a8, g_a8);
    cudaGetSymbolAddress((void**)&w8, g_w8);

    {
        int n16 = M_DIM * D_DIM / 16;           // 6,291,456
        conv_sign_A<<<(n16 + 255) / 256, 256>>>(inp, a8, n16);
    }
    {
        int n16 = NP * D_DIM / 16;              // 786,432
        conv_sign_W<<<(n16 + 255) / 256, 256>>>(wt, w8);
    }

    static bool attr_set = false;
    if (!attr_set) {
        cudaFuncSetAttribute(bgemm_imma_kernel,
                             cudaFuncAttributeMaxDynamicSharedMemorySize, SMEM_REQ);
        attr_set = true;
    }
    // grid x = N tiles (8), y = M tiles (32); x-fastest keeps A tiles hot in L2.
    dim3 grid(NP / TN, M_DIM / TM);
    bgemm_imma_kernel<<<grid, 512, SMEM_REQ>>>(a8, w8, out);
}

// round 9
// speedup vs baseline: 2.6985x; 2.6985x over previous
#include <cuda_runtime.h>
#include <cstdint>

// ---------------------------------------------------------------------------
// out[8192,1000] = sign(X) @ sign(W)^T via bit-packing + XOR + CSA-popcount.
// dot = D - 2 * popc(a ^ b). CSA (Harley-Seal) over 8-word groups halves the
// POPC count (quarter-rate pipe); XOR/LOP3 on full-rate alu; accumulate on fma.
// cp.async double-buffered tiles overlap global loads with compute.
// ---------------------------------------------------------------------------
#define M_DIM 8192
#define N_DIM 1000
#define NP    1024
#define D_DIM 12288
#define KW    384            // 32-bit words per row
#define KCW   32             // words per K-chunk
#define NCH   12             // KW / KCW
#define RSB   144            // smem row stride bytes (36 words: conflict-free)
#define TILE_B   (128 * RSB)            // 18432 per operand tile
#define STAGE_B  (2 * TILE_B)           // 36864 (A + B)
#define SMEM_REQ (2 * STAGE_B)          // 73728 (2 stages)

__device__ uint32_t g_bitsA[(size_t)M_DIM * KW];   // 12.6 MB
__device__ uint32_t g_bitsW[(size_t)NP * KW];      // 1.6 MB (padded, pad rows = 0)

// ============================ helpers ======================================
__device__ __forceinline__ uint32_t smem_to_u32(const void* p) {
    uint32_t a;
    asm("{ .reg .u64 t; cvta.to.shared.u64 t, %1; cvt.u32.u64 %0, t; }"
        : "=r"(a) : "l"(p));
    return a;
}
__device__ __forceinline__ void cp_async16(uint32_t saddr, const void* gptr) {
    asm volatile("cp.async.cg.shared.global [%0], [%1], 16;"
                 :: "r"(saddr), "l"(gptr));
}
#define CP_COMMIT() asm volatile("cp.async.commit_group;" ::: "memory")
#define CP_WAIT1()  asm volatile("cp.async.wait_group 1;" ::: "memory")

__device__ __forceinline__ uint32_t maj3(uint32_t x, uint32_t y, uint32_t z) {
    return (x & y) | (x & z) | (y & z);   // single LOP3
}

// =========================== pack kernels ==================================
// Each warp packs 4 words (128 floats); ballot is warp-uniform, lane 0 stores 16B.
__global__ __launch_bounds__(256)
void pack_sign_A(const float* __restrict__ in, uint32_t* __restrict__ out,
                 int nwords) {
    int warp_id = (blockIdx.x * blockDim.x + threadIdx.x) >> 5;
    int lane    = threadIdx.x & 31;
    int w0 = warp_id * 4;
    if (w0 >= nwords) return;
    const float* base = in + (size_t)w0 * 32;
    uint32_t w[4];
#pragma unroll
    for (int c = 0; c < 4; c++)
        w[c] = __ballot_sync(0xffffffffu, base[c * 32 + lane] > 0.0f);
    if (lane == 0)
        *reinterpret_cast<uint4*>(out + w0) = make_uint4(w[0], w[1], w[2], w[3]);
}

// W packed into NP=1024 rows; rows >= N_DIM are zero (outputs masked at store).
__global__ __launch_bounds__(256)
void pack_sign_W(const float* __restrict__ in, uint32_t* __restrict__ out) {
    int warp_id = (blockIdx.x * blockDim.x + threadIdx.x) >> 5;
    int lane    = threadIdx.x & 31;
    int w0 = warp_id * 4;                  // KW divisible by 4 -> same row
    if (w0 >= NP * KW) return;
    int row = w0 / KW;
    uint32_t w[4] = {0u, 0u, 0u, 0u};
    if (row < N_DIM) {
        const float* base = in + (size_t)w0 * 32;
#pragma unroll
        for (int c = 0; c < 4; c++)
            w[c] = __ballot_sync(0xffffffffu, base[c * 32 + lane] > 0.0f);
    }
    if (lane == 0)
        *reinterpret_cast<uint4*>(out + w0) = make_uint4(w[0], w[1], w[2], w[3]);
}

// ============================== GEMM =======================================
// 128x128 tile, 256 threads, 8x8 micro-tile. K chunks of 32 words, CSA over
// 8-word groups, j-loop split in halves of 4 to bound register pressure.
__global__ __launch_bounds__(256, 2)
void bgemm_csa_kernel(const uint32_t* __restrict__ Ab,
                      const uint32_t* __restrict__ Wb,
                      float* __restrict__ out)
{
    extern __shared__ char smem[];
    const uint32_t sbase = smem_to_u32(smem);
    const int tid = threadIdx.x;
    const int tx  = tid & 15;
    const int ty  = tid >> 4;
    const int mBase = blockIdx.y * 128;
    const int nBase = blockIdx.x * 128;

    int acc[8][8];
#pragma unroll
    for (int i = 0; i < 8; i++)
#pragma unroll
        for (int j = 0; j < 8; j++) acc[i][j] = 0;

    // --- stage loader: A/B 128 rows x 32 words, 16B cp.async units ---------
    auto load_stage = [&](int stage, int chunk) {
        const uint32_t sA = sbase + stage * STAGE_B;
        const uint32_t sB = sA + TILE_B;
        const int kw = chunk * KCW;
#pragma unroll
        for (int l = 0; l < 4; l++) {           // 1024 units, 4 per thread
            int u = tid + l * 256;
            int row = u >> 3, c = u & 7;
            uint32_t d = (uint32_t)(row * RSB + c * 16);
            cp_async16(sA + d, Ab + (size_t)(mBase + row) * KW + kw + c * 4);
            cp_async16(sB + d, Wb + (size_t)(nBase + row) * KW + kw + c * 4);
        }
    };

    // --- compute one 32-word chunk -----------------------------------------
    auto compute_stage = [&](int stage) {
        const uint32_t sA = sbase + stage * STAGE_B;
        const uint32_t sB = sA + TILE_B;
#pragma unroll
        for (int g = 0; g < 4; g++) {           // 8-word groups
            const int kb = g * 32;              // byte offset of group
#pragma unroll
            for (int jh = 0; jh < 2; jh++) {
                uint32_t b[4][8];
#pragma unroll
                for (int j0 = 0; j0 < 4; j0++) {
                    uint32_t r = sB + (uint32_t)((tx + 16 * (jh * 4 + j0)) * RSB + kb);
                    uint4 t0 = *reinterpret_cast<const uint4*>((const char*)smem +
                                   (r - sbase));
                    uint4 t1 = *reinterpret_cast<const uint4*>((const char*)smem +
                                   (r - sbase) + 16);
                    b[j0][0] = t0.x; b[j0][1] = t0.y; b[j0][2] = t0.z; b[j0][3] = t0.w;
                    b[j0][4] = t1.x; b[j0][5] = t1.y; b[j0][6] = t1.z; b[j0][7] = t1.w;
                }
#pragma unroll
                for (int i = 0; i < 8; i++) {
                    uint32_t r = sA + (uint32_t)((ty + 16 * i) * RSB + kb);
                    uint4 a0 = *reinterpret_cast<const uint4*>((const char*)smem +
                                   (r - sbase));
                    uint4 a1 = *reinterpret_cast<const uint4*>((const char*)smem +
                                   (r - sbase) + 16);
                    uint32_t aw[8] = {a0.x, a0.y, a0.z, a0.w, a1.x, a1.y, a1.z, a1.w};
#pragma unroll
                    for (int j0 = 0; j0 < 4; j0++) {
                        uint32_t x0 = aw[0] ^ b[j0][0], x1 = aw[1] ^ b[j0][1];
                        uint32_t x2 = aw[2] ^ b[j0][2], x3 = aw[3] ^ b[j0][3];
                        uint32_t x4 = aw[4] ^ b[j0][4], x5 = aw[5] ^ b[j0][5];
                        uint32_t x6 = aw[6] ^ b[j0][6], x7 = aw[7] ^ b[j0][7];
                        // CSA tree: 8 words -> 1 weight-1 + 3 weight-2/4 words
                        uint32_t s1 = x0 ^ x1 ^ x2, c1 = maj3(x0, x1, x2);
                        uint32_t s2 = x3 ^ x4 ^ x5, c2 = maj3(x3, x4, x5);
                        uint32_t s3 = s1 ^ s2 ^ x6, c3 = maj3(s1, s2, x6);
                        uint32_t s4 = s3 ^ x7,      c4 = s3 & x7;
                        uint32_t cs = c1 ^ c2 ^ c3, cc = maj3(c1, c2, c3);
                        uint32_t cs2 = cs ^ c4,     cc2 = cs & c4;
                        int p1 = __popc(s4);
                        int p2 = __popc(cs2);
                        int p4 = __popc(cc) + __popc(cc2);
                        acc[i][jh * 4 + j0] += p1 + 2 * p2 + 4 * p4;
                    }
                }
            }
        }
    };

    // --- 2-stage pipeline ---------------------------------------------------
    load_stage(0, 0); CP_COMMIT();
    for (int i = 0; i < NCH; i++) {
        if (i + 1 < NCH) load_stage((i + 1) & 1, i + 1);
        CP_COMMIT();
        CP_WAIT1();
        __syncthreads();
        compute_stage(i & 1);
        __syncthreads();
    }

    // --- epilogue: dot = D - 2*mismatches, pad columns masked ---------------
#pragma unroll
    for (int i = 0; i < 8; i++) {
        int m = mBase + ty + 16 * i;
#pragma unroll
        for (int j = 0; j < 8; j++) {
            int n = nBase + tx + 16 * j;
            if (n < N_DIM)
                out[(size_t)m * N_DIM + n] = (float)(D_DIM - 2 * acc[i][j]);
        }
    }
}

// =============================== launcher ==================================
extern "C" void kernel_launch(void* const* d_in, const int* in_sizes, int n_in,
                              void* d_out, int out_size) {
    const float* inp = (const float*)d_in[0];   // [8192, 12288]
    const float* wt  = (const float*)d_in[1];   // [1000, 12288]
    float* out = (float*)d_out;                 // [8192, 1000]

    uint32_t* bitsA = nullptr;
    uint32_t* bitsW = nullptr;
    cudaGetSymbolAddress((void**)&bitsA, g_bitsA);
    cudaGetSymbolAddress((void**)&bitsW, g_bitsW);

    {   // pack A: 3,145,728 words, 4 per warp
        int nwords = M_DIM * KW;
        int blocks = (nwords / 4 * 32 + 255) / 256;
        pack_sign_A<<<blocks, 256>>>(inp, bitsA, nwords);
    }
    {   // pack W padded to 1024 rows
        int nwords = NP * KW;
        int blocks = (nwords / 4 * 32 + 255) / 256;
        pack_sign_W<<<blocks, 256>>>(wt, bitsW);
    }

    static bool attr_set = false;
    if (!attr_set) {
        cudaFuncSetAttribute(bgemm_csa_kernel,
                             cudaFuncAttributeMaxDynamicSharedMemorySize, SMEM_REQ);
        attr_set = true;
    }
    // grid x = N tiles (8, fastest -> A-tile L2 reuse), y = M tiles (64)
    dim3 grid(NP / 128, M_DIM / 128);
    bgemm_csa_kernel<<<grid, 256, SMEM_REQ>>>(bitsA, bitsW, out);
}